// round 2
// baseline (speedup 1.0000x reference)
#include <cuda_runtime.h>
#include <math.h>

// Problem constants
#define T_STEPS 256
#define BATCH   256
#define NH      1024      // N_RNN
#define KIN     105       // RULE_START + N_RULE
#define RS      85        // RULE_START
#define NRULE   20
#define NOUT    33
#define TBROWS  (T_STEPS*BATCH)   // 65536
#define BH      (BATCH*NH)        // 262144
#define KSPLIT  8

// ---------------- scratch (static device allocations only) ----------------
__device__ float g_pre[(long long)TBROWS*NH];   // 256 MB: inp + noise + b_sens + b_rec
__device__ float g_hid[(long long)TBROWS*NH];   // 256 MB: hidden states for final GEMM
__device__ float g_part[KSPLIT*BH];             // 8 MB : split-K partials per step
__device__ float g_h0[BH];
__device__ float g_h1[BH];

// =======================================================================
// Kernel A: g_pre = x @ [W_sens | W_rule]^T + b_sens + b_rec + noise
// GEMM M=65536, K=105, N=1024.  BM=128, BN=64, 256 threads, 8x4 micro.
// Full K kept in smem (dynamic, 84 KB).
// =======================================================================
#define A_SA_STRIDE 132
#define A_SB_STRIDE 68
#define A_SMEM_BYTES ((105*A_SA_STRIDE + 105*A_SB_STRIDE)*4)

__global__ void kernelA(const float* __restrict__ x,
                        const float* __restrict__ noise,
                        const float* __restrict__ Wsens,
                        const float* __restrict__ Wrule,
                        const float* __restrict__ bsens,
                        const float* __restrict__ brec)
{
    extern __shared__ float sm[];
    float* sA = sm;                      // [105][132]  (k-major, padded)
    float* sB = sm + 105*A_SA_STRIDE;    // [105][68]

    const int tid = threadIdx.x;             // 256 threads
    const int m0  = blockIdx.y * 128;
    const int n0  = blockIdx.x * 64;

    // Load A tile (128 rows x 105 k) -> sA[k][m]
    for (int idx = tid; idx < 128*105; idx += 256) {
        int m = idx / 105, k = idx - m*105;
        sA[k*A_SA_STRIDE + m] = x[(m0 + m)*KIN + k];
    }
    // Load combined weight tile Wc[n][k] -> sB[k][n]
    for (int idx = tid; idx < 64*105; idx += 256) {
        int n = idx / 105, k = idx - n*105;
        float v = (k < RS) ? Wsens[(n0 + n)*RS + k]
                           : Wrule[(n0 + n)*NRULE + (k - RS)];
        sB[k*A_SB_STRIDE + n] = v;
    }
    __syncthreads();

    const int ty = tid >> 4;   // 0..15 -> rows ty*8..+7
    const int tx = tid & 15;   // 0..15 -> cols tx*4..+3

    float acc[8][4];
#pragma unroll
    for (int i = 0; i < 8; i++)
#pragma unroll
        for (int j = 0; j < 4; j++) acc[i][j] = 0.f;

#pragma unroll 5
    for (int k = 0; k < 105; k++) {
        float4 a0 = *(const float4*)&sA[k*A_SA_STRIDE + ty*8];
        float4 a1 = *(const float4*)&sA[k*A_SA_STRIDE + ty*8 + 4];
        float4 b  = *(const float4*)&sB[k*A_SB_STRIDE + tx*4];
        float av[8] = {a0.x,a0.y,a0.z,a0.w,a1.x,a1.y,a1.z,a1.w};
        float bv[4] = {b.x,b.y,b.z,b.w};
#pragma unroll
        for (int i = 0; i < 8; i++)
#pragma unroll
            for (int j = 0; j < 4; j++)
                acc[i][j] = fmaf(av[i], bv[j], acc[i][j]);
    }

    // epilogue: + b_sens + b_rec + noise
    float bias[4];
#pragma unroll
    for (int j = 0; j < 4; j++) {
        int col = n0 + tx*4 + j;
        bias[j] = bsens[col] + brec[col];
    }
#pragma unroll
    for (int i = 0; i < 8; i++) {
        int row = m0 + ty*8 + i;
        long long base = (long long)row*NH + n0 + tx*4;
#pragma unroll
        for (int j = 0; j < 4; j++)
            g_pre[base + j] = acc[i][j] + bias[j] + noise[base + j];
    }
}

// =======================================================================
// Zero initial hidden state
// =======================================================================
__global__ void kzero()
{
    int i = blockIdx.x * blockDim.x + threadIdx.x;
    if (i < BH) g_h0[i] = 0.f;
}

// =======================================================================
// Step stage 1: split-K GEMM  part[kz] = h_in @ W_rec^T (K range of 128)
// BM=64 (batch), BN=64 (j), 128 threads, 8x4 micro, KB=32.
// grid = (16 ntiles, 4 mtiles, 8 ksplit)
// =======================================================================
#define S_STRIDE 68

__global__ void kstep1(const float* __restrict__ Wrec, int t)
{
    __shared__ float sH[32*S_STRIDE];
    __shared__ float sW[32*S_STRIDE];

    const float* __restrict__ hin = (t & 1) ? g_h1 : g_h0;

    const int tid = threadIdx.x;            // 128 threads
    const int n0  = blockIdx.x * 64;
    const int b0  = blockIdx.y * 64;
    const int kz  = blockIdx.z;
    const int k0  = kz * 128;

    const int ty = tid >> 4;   // 0..7  -> rows ty*8..+7  (64 rows)
    const int tx = tid & 15;   // 0..15 -> cols tx*4..+3  (64 cols)

    float acc[8][4];
#pragma unroll
    for (int i = 0; i < 8; i++)
#pragma unroll
        for (int j = 0; j < 4; j++) acc[i][j] = 0.f;

    for (int kc = 0; kc < 128; kc += 32) {
        __syncthreads();
#pragma unroll
        for (int i = 0; i < 16; i++) {
            int idx = i*128 + tid;        // 0..2047
            int kk = idx & 31;
            int r  = idx >> 5;            // 0..63
            sH[kk*S_STRIDE + r] = hin[(b0 + r)*NH + k0 + kc + kk];
            sW[kk*S_STRIDE + r] = Wrec[(n0 + r)*NH + k0 + kc + kk];
        }
        __syncthreads();

#pragma unroll 8
        for (int kk = 0; kk < 32; kk++) {
            float4 a0 = *(const float4*)&sH[kk*S_STRIDE + ty*8];
            float4 a1 = *(const float4*)&sH[kk*S_STRIDE + ty*8 + 4];
            float4 b  = *(const float4*)&sW[kk*S_STRIDE + tx*4];
            float av[8] = {a0.x,a0.y,a0.z,a0.w,a1.x,a1.y,a1.z,a1.w};
            float bv[4] = {b.x,b.y,b.z,b.w};
#pragma unroll
            for (int i = 0; i < 8; i++)
#pragma unroll
                for (int j = 0; j < 4; j++)
                    acc[i][j] = fmaf(av[i], bv[j], acc[i][j]);
        }
    }

    float* __restrict__ outp = g_part + kz*BH;
#pragma unroll
    for (int i = 0; i < 8; i++) {
        int row = b0 + ty*8 + i;
        float4 v = make_float4(acc[i][0], acc[i][1], acc[i][2], acc[i][3]);
        *(float4*)&outp[row*NH + n0 + tx*4] = v;
    }
}

// =======================================================================
// Step stage 2: reduce partials, softplus, leaky update, store hidden
// =======================================================================
__global__ void kstep2(int t)
{
    int i = blockIdx.x * blockDim.x + threadIdx.x;   // 0..BH-1
    const float* __restrict__ hin  = (t & 1) ? g_h1 : g_h0;
    float*       __restrict__ hout = (t & 1) ? g_h0 : g_h1;

    float s = g_pre[(long long)t*BH + i];
#pragma unroll
    for (int z = 0; z < KSPLIT; z++) s += g_part[z*BH + i];

    // numerically stable softplus: log1p(exp(x))
    float sp = fmaxf(s, 0.f) + log1pf(expf(-fabsf(s)));
    float h  = 0.2f * sp + 0.8f * hin[i];

    hout[i] = h;
    g_hid[(long long)t*BH + i] = h;
}

// =======================================================================
// Final: out = hid @ W_out^T + b_out.  M=65536, K=1024, N=33.
// 256 threads/block, 2 rows/thread (512 rows/block), KB=16, W broadcast.
// =======================================================================
__global__ void kfinal(const float* __restrict__ Wout,
                       const float* __restrict__ bout,
                       float* __restrict__ out)
{
    __shared__ float sA[512*17];
    __shared__ float sW[33*17];

    const int tid = threadIdx.x;          // 256
    const int r0  = blockIdx.x * 512;

    float acc0[NOUT], acc1[NOUT];
#pragma unroll
    for (int o = 0; o < NOUT; o++) { acc0[o] = 0.f; acc1[o] = 0.f; }

    const int ra = tid*2, rb = tid*2 + 1;

    for (int kc = 0; kc < NH; kc += 16) {
        __syncthreads();
#pragma unroll
        for (int i = 0; i < 32; i++) {
            int idx = i*256 + tid;        // 0..8191
            int r  = idx >> 4;
            int kk = idx & 15;
            sA[r*17 + kk] = g_hid[(long long)(r0 + r)*NH + kc + kk];
        }
        for (int idx = tid; idx < NOUT*16; idx += 256) {
            int o  = idx >> 4;
            int kk = idx & 15;
            sW[o*17 + kk] = Wout[o*NH + kc + kk];
        }
        __syncthreads();

#pragma unroll 4
        for (int kk = 0; kk < 16; kk++) {
            float a0 = sA[ra*17 + kk];
            float a1 = sA[rb*17 + kk];
#pragma unroll
            for (int o = 0; o < NOUT; o++) {
                float w = sW[o*17 + kk];
                acc0[o] = fmaf(a0, w, acc0[o]);
                acc1[o] = fmaf(a1, w, acc1[o]);
            }
        }
    }

#pragma unroll
    for (int o = 0; o < NOUT; o++) {
        out[(long long)(r0 + ra)*NOUT + o] = acc0[o] + bout[o];
        out[(long long)(r0 + rb)*NOUT + o] = acc1[o] + bout[o];
    }
}

// =======================================================================
// launch
// =======================================================================
extern "C" void kernel_launch(void* const* d_in, const int* in_sizes, int n_in,
                              void* d_out, int out_size)
{
    const float* x     = (const float*)d_in[0];
    const float* noise = (const float*)d_in[1];
    const float* Wsens = (const float*)d_in[2];
    const float* bsens = (const float*)d_in[3];
    const float* Wrule = (const float*)d_in[4];
    const float* Wrec  = (const float*)d_in[5];
    const float* brec  = (const float*)d_in[6];
    const float* Wout  = (const float*)d_in[7];
    const float* bout  = (const float*)d_in[8];
    float* out = (float*)d_out;

    cudaFuncSetAttribute(kernelA, cudaFuncAttributeMaxDynamicSharedMemorySize,
                         A_SMEM_BYTES);

    // pre-activations (+noise +biases) for all timesteps
    kernelA<<<dim3(16, 512), 256, A_SMEM_BYTES>>>(x, noise, Wsens, Wrule, bsens, brec);

    // h0 = 0
    kzero<<<BH/256, 256>>>();

    // sequential recurrence
    for (int t = 0; t < T_STEPS; t++) {
        kstep1<<<dim3(16, 4, KSPLIT), 128>>>(Wrec, t);
        kstep2<<<BH/256, 256>>>(t);
    }

    // output projection
    kfinal<<<TBROWS/512, 256>>>(Wout, bout, out);
}

// round 4
// speedup vs baseline: 1.5078x; 1.5078x over previous
#include <cuda_runtime.h>
#include <cuda_bf16.h>
#include <math.h>
#include <stdint.h>

// Problem constants
#define T_STEPS 256
#define BATCH   256
#define NH      1024
#define KIN     105
#define RS      85
#define NRULE   20
#define NOUT    33
#define TBROWS  (T_STEPS*BATCH)   // 65536
#define BH      (BATCH*NH)        // 262144

// ---------------- scratch (static device allocations only) ----------------
__device__ float g_pre[(long long)TBROWS*NH];   // 256 MB
__device__ float g_hid[(long long)TBROWS*NH];   // 256 MB
__device__ __nv_bfloat16 g_Whi[NH*NH];
__device__ __nv_bfloat16 g_Wlo[NH*NH];
__device__ __nv_bfloat16 g_hhi[BH];
__device__ __nv_bfloat16 g_hlo[BH];
__device__ unsigned g_bar;

// ======================= helpers ===========================================
__device__ __forceinline__ uint32_t smem_u32(const void* p) {
    uint32_t a;
    asm("{ .reg .u64 t; cvta.to.shared.u64 t, %1; cvt.u32.u64 %0, t; }"
        : "=r"(a) : "l"(p));
    return a;
}
__device__ __forceinline__ void cp_async16(uint32_t dst, const void* src) {
    asm volatile("cp.async.cg.shared.global [%0], [%1], 16;"
                 :: "r"(dst), "l"(src) : "memory");
}
__device__ __forceinline__ void cp_commit() {
    asm volatile("cp.async.commit_group;" ::: "memory");
}
template<int N> __device__ __forceinline__ void cp_wait() {
    asm volatile("cp.async.wait_group %0;" :: "n"(N) : "memory");
}
__device__ __forceinline__ void ldmat4(uint32_t& r0, uint32_t& r1,
                                       uint32_t& r2, uint32_t& r3, uint32_t a) {
    asm volatile("ldmatrix.sync.aligned.m8n8.x4.shared.b16 {%0,%1,%2,%3}, [%4];"
                 : "=r"(r0), "=r"(r1), "=r"(r2), "=r"(r3) : "r"(a));
}
__device__ __forceinline__ void mma16816(float* c, const uint32_t* a,
                                         const uint32_t* b) {
    asm volatile(
        "mma.sync.aligned.m16n8k16.row.col.f32.bf16.bf16.f32 "
        "{%0,%1,%2,%3}, {%4,%5,%6,%7}, {%8,%9}, {%0,%1,%2,%3};"
        : "+f"(c[0]), "+f"(c[1]), "+f"(c[2]), "+f"(c[3])
        : "r"(a[0]), "r"(a[1]), "r"(a[2]), "r"(a[3]), "r"(b[0]), "r"(b[1]));
}

// ======================= kernelA: pre-activations ==========================
#define A_SA_STRIDE 132
#define A_SB_STRIDE 68
#define A_SMEM_BYTES ((105*A_SA_STRIDE + 105*A_SB_STRIDE)*4)

__global__ void kernelA(const float* __restrict__ x,
                        const float* __restrict__ noise,
                        const float* __restrict__ Wsens,
                        const float* __restrict__ Wrule,
                        const float* __restrict__ bsens,
                        const float* __restrict__ brec)
{
    extern __shared__ float sm[];
    float* sA = sm;
    float* sB = sm + 105*A_SA_STRIDE;

    const int tid = threadIdx.x;
    const int m0  = blockIdx.y * 128;
    const int n0  = blockIdx.x * 64;

    for (int idx = tid; idx < 128*105; idx += 256) {
        int m = idx / 105, k = idx - m*105;
        sA[k*A_SA_STRIDE + m] = x[(m0 + m)*KIN + k];
    }
    for (int idx = tid; idx < 64*105; idx += 256) {
        int n = idx / 105, k = idx - n*105;
        float v = (k < RS) ? Wsens[(n0 + n)*RS + k]
                           : Wrule[(n0 + n)*NRULE + (k - RS)];
        sB[k*A_SB_STRIDE + n] = v;
    }
    __syncthreads();

    const int ty = tid >> 4;
    const int tx = tid & 15;

    float acc[8][4];
#pragma unroll
    for (int i = 0; i < 8; i++)
#pragma unroll
        for (int j = 0; j < 4; j++) acc[i][j] = 0.f;

#pragma unroll 5
    for (int k = 0; k < 105; k++) {
        float4 a0 = *(const float4*)&sA[k*A_SA_STRIDE + ty*8];
        float4 a1 = *(const float4*)&sA[k*A_SA_STRIDE + ty*8 + 4];
        float4 b  = *(const float4*)&sB[k*A_SB_STRIDE + tx*4];
        float av[8] = {a0.x,a0.y,a0.z,a0.w,a1.x,a1.y,a1.z,a1.w};
        float bv[4] = {b.x,b.y,b.z,b.w};
#pragma unroll
        for (int i = 0; i < 8; i++)
#pragma unroll
            for (int j = 0; j < 4; j++)
                acc[i][j] = fmaf(av[i], bv[j], acc[i][j]);
    }

    float bias[4];
#pragma unroll
    for (int j = 0; j < 4; j++) {
        int col = n0 + tx*4 + j;
        bias[j] = bsens[col] + brec[col];
    }
#pragma unroll
    for (int i = 0; i < 8; i++) {
        int row = m0 + ty*8 + i;
        long long base = (long long)row*NH + n0 + tx*4;
#pragma unroll
        for (int j = 0; j < 4; j++)
            g_pre[base + j] = acc[i][j] + bias[j] + noise[base + j];
    }
}

// ======================= prep ==============================================
__global__ void kprep(const float* __restrict__ Wrec)
{
    int i = blockIdx.x * 256 + threadIdx.x;
    float w = Wrec[i];
    __nv_bfloat16 hi = __float2bfloat16(w);
    g_Whi[i] = hi;
    g_Wlo[i] = __float2bfloat16(w - __bfloat162float(hi));
    if (i == 0) g_bar = 0;
}

// ======================= krnn: persistent recurrence =======================
// 128 CTAs (8 m-tiles x 16 n-tiles), tile 32x64, full K=1024 in 16 chunks
// of 64. Whi n-slice persists in smem; hhi/hlo/wlo double-buffered cp.async.
// 3-term double-bf16 HMMA: Ahi*Bhi + Ahi*Blo + Alo*Bhi.
#define NCTA    128
#define BM      32
#define BN      64
#define BKC     64
#define NCHUNK  16
// streamed buffer layout (144B row pitch for conflict-free ldmatrix)
#define SM_HHI  0
#define SM_HLO  4608
#define SM_WLO  9216
#define SM_BUF  18432
// persistent Whi: 64 rows x 2064B pitch
#define SM_WHIP (2*SM_BUF)
#define WHI_PITCH 2064
#define RNN_SMEM (SM_WHIP + 64*WHI_PITCH)   // 36864 + 132096 = 168960

__device__ __forceinline__ void load_chunk(uint32_t bufb, int m0, int n0,
                                           int kc, int tid)
{
#pragma unroll
    for (int i = 0; i < 4; i++) {          // hhi + hlo : 512 x 16B
        int v   = i*128 + tid;
        int arr = v >> 8;                  // 0 hi, 1 lo
        int r   = (v >> 3) & 31;
        int ch  = v & 7;
        const __nv_bfloat16* src =
            (arr ? g_hlo : g_hhi) + (long long)(m0 + r)*NH + kc + ch*8;
        cp_async16(bufb + (arr ? SM_HLO : SM_HHI) + r*144 + ch*16, src);
    }
#pragma unroll
    for (int i = 0; i < 4; i++) {          // wlo : 512 x 16B
        int v  = i*128 + tid;
        int r  = (v >> 3) & 63;
        int ch = v & 7;
        const __nv_bfloat16* src =
            g_Wlo + (long long)(n0 + r)*NH + kc + ch*8;
        cp_async16(bufb + SM_WLO + r*144 + ch*16, src);
    }
}

__global__ void __launch_bounds__(128, 1) krnn()
{
    extern __shared__ __align__(128) char smraw[];
    const uint32_t sb  = smem_u32(smraw);
    const int tid  = threadIdx.x;
    const int wid  = tid >> 5;
    const int lane = tid & 31;
    const int m0   = (blockIdx.x >> 4) * BM;
    const int n0   = (blockIdx.x & 15) * BN;

    // ---- one-time: persistent Whi slice (64 rows x 2048B) ----
    for (int i = 0; i < 64; i++) {
        int v  = i*128 + tid;              // 0..8191
        int r  = v >> 7;
        int ch = v & 127;
        cp_async16(sb + SM_WHIP + r*WHI_PITCH + ch*16,
                   g_Whi + (long long)(n0 + r)*NH + ch*8);
    }
    cp_commit();
    cp_wait<0>();
    __syncthreads();

    // A/B ldmatrix lane addressing (within-tile offsets)
    const int aRow  = lane & 15;
    const int aKoff = ((lane >> 4) & 1) * 16;
    const int bRow  = wid*16 + ((lane >> 4) & 1)*8 + (lane & 7);
    const int bKoff = ((lane >> 3) & 1) * 16;

    // epilogue element coords
    const int rBase = lane >> 2;             // + mi*16 (+8)
    const int cBase = wid*16 + (lane & 3)*2; // + ni*8

    float hp[2][2][4];
#pragma unroll
    for (int a = 0; a < 2; a++)
#pragma unroll
        for (int b = 0; b < 2; b++)
#pragma unroll
            for (int e = 0; e < 4; e++) hp[a][b][e] = 0.f;

#pragma unroll 1
    for (int t = 0; t < T_STEPS; t++) {
        float acc[2][2][4];
#pragma unroll
        for (int a = 0; a < 2; a++)
#pragma unroll
            for (int b = 0; b < 2; b++)
#pragma unroll
                for (int e = 0; e < 4; e++) acc[a][b][e] = 0.f;

        if (t > 0) {
            load_chunk(sb, m0, n0, 0, tid);
            cp_commit();
#pragma unroll 1
            for (int c = 0; c < NCHUNK; c++) {
                if (c + 1 < NCHUNK) {
                    load_chunk(sb + ((c + 1) & 1)*SM_BUF, m0, n0,
                               (c + 1)*BKC, tid);
                    cp_commit();
                    cp_wait<1>();
                } else {
                    cp_wait<0>();
                }
                __syncthreads();
                const uint32_t bb = sb + (c & 1)*SM_BUF;
#pragma unroll
                for (int q = 0; q < 4; q++) {
                    uint32_t ah[2][4], al[2][4], bh[2][2], bl[2][2];
#pragma unroll
                    for (int mi = 0; mi < 2; mi++) {
                        uint32_t ar = (mi*16 + aRow)*144 + q*32 + aKoff;
                        ldmat4(ah[mi][0], ah[mi][1], ah[mi][2], ah[mi][3],
                               bb + SM_HHI + ar);
                        ldmat4(al[mi][0], al[mi][1], al[mi][2], al[mi][3],
                               bb + SM_HLO + ar);
                    }
                    ldmat4(bh[0][0], bh[0][1], bh[1][0], bh[1][1],
                           sb + SM_WHIP + bRow*WHI_PITCH
                              + c*128 + q*32 + bKoff);
                    ldmat4(bl[0][0], bl[0][1], bl[1][0], bl[1][1],
                           bb + SM_WLO + bRow*144 + q*32 + bKoff);
#pragma unroll
                    for (int mi = 0; mi < 2; mi++)
#pragma unroll
                        for (int ni = 0; ni < 2; ni++) {
                            mma16816(acc[mi][ni], ah[mi], bh[ni]);
                            mma16816(acc[mi][ni], ah[mi], bl[ni]);
                            mma16816(acc[mi][ni], al[mi], bh[ni]);
                        }
                }
                __syncthreads();
            }
        }

        // ---- fused epilogue ----
        const float* __restrict__ pre = g_pre + (long long)t*BH;
        float*       __restrict__ hid = g_hid + (long long)t*BH;
#pragma unroll
        for (int mi = 0; mi < 2; mi++)
#pragma unroll
            for (int ni = 0; ni < 2; ni++)
#pragma unroll
                for (int e = 0; e < 2; e++) {
                    int row = m0 + mi*16 + rBase + e*8;
                    int col = n0 + ni*8 + cBase;
                    long long g = (long long)row*NH + col;
                    float2 pr = *(const float2*)(pre + g);
                    float s0 = acc[mi][ni][e*2+0] + pr.x;
                    float s1 = acc[mi][ni][e*2+1] + pr.y;
                    float sp0 = fmaxf(s0, 0.f) + log1pf(expf(-fabsf(s0)));
                    float sp1 = fmaxf(s1, 0.f) + log1pf(expf(-fabsf(s1)));
                    float h0 = 0.2f*sp0 + 0.8f*hp[mi][ni][e*2+0];
                    float h1 = 0.2f*sp1 + 0.8f*hp[mi][ni][e*2+1];
                    hp[mi][ni][e*2+0] = h0;
                    hp[mi][ni][e*2+1] = h1;
                    float2 hv; hv.x = h0; hv.y = h1;
                    *(float2*)(hid + g) = hv;
                    __nv_bfloat16 h0h = __float2bfloat16(h0);
                    __nv_bfloat16 h1h = __float2bfloat16(h1);
                    uint32_t hi2 = ((uint32_t)__bfloat16_as_ushort(h1h) << 16)
                                 | __bfloat16_as_ushort(h0h);
                    *(uint32_t*)(g_hhi + g) = hi2;
                    __nv_bfloat16 l0 =
                        __float2bfloat16(h0 - __bfloat162float(h0h));
                    __nv_bfloat16 l1 =
                        __float2bfloat16(h1 - __bfloat162float(h1h));
                    uint32_t lo2 = ((uint32_t)__bfloat16_as_ushort(l1) << 16)
                                 | __bfloat16_as_ushort(l0);
                    *(uint32_t*)(g_hlo + g) = lo2;
                }

        // ---- grid barrier (skip after last step) ----
        if (t < T_STEPS - 1) {
            __syncthreads();
            if (tid == 0) {
                __threadfence();
                atomicAdd(&g_bar, 1u);
                const unsigned target = (unsigned)(t + 1) * NCTA;
                unsigned v;
                do {
                    asm volatile("ld.acquire.gpu.u32 %0, [%1];"
                                 : "=r"(v) : "l"(&g_bar));
                    if (v < target) __nanosleep(64);
                } while (v < target);
            }
            __syncthreads();
        }
    }
}

// ======================= kfinal: output projection =========================
__global__ void kfinal(const float* __restrict__ Wout,
                       const float* __restrict__ bout,
                       float* __restrict__ out)
{
    __shared__ float sA[512*17];
    __shared__ float sW[33*17];

    const int tid = threadIdx.x;
    const int r0  = blockIdx.x * 512;

    float acc0[NOUT], acc1[NOUT];
#pragma unroll
    for (int o = 0; o < NOUT; o++) { acc0[o] = 0.f; acc1[o] = 0.f; }

    const int ra = tid*2, rb = tid*2 + 1;

    for (int kc = 0; kc < NH; kc += 16) {
        __syncthreads();
#pragma unroll
        for (int i = 0; i < 32; i++) {
            int idx = i*256 + tid;
            int r  = idx >> 4;
            int kk = idx & 15;
            sA[r*17 + kk] = g_hid[(long long)(r0 + r)*NH + kc + kk];
        }
        for (int idx = tid; idx < NOUT*16; idx += 256) {
            int o  = idx >> 4;
            int kk = idx & 15;
            sW[o*17 + kk] = Wout[o*NH + kc + kk];
        }
        __syncthreads();

#pragma unroll 4
        for (int kk = 0; kk < 16; kk++) {
            float a0 = sA[ra*17 + kk];
            float a1 = sA[rb*17 + kk];
#pragma unroll
            for (int o = 0; o < NOUT; o++) {
                float w = sW[o*17 + kk];
                acc0[o] = fmaf(a0, w, acc0[o]);
                acc1[o] = fmaf(a1, w, acc1[o]);
            }
        }
    }

#pragma unroll
    for (int o = 0; o < NOUT; o++) {
        out[(long long)(r0 + ra)*NOUT + o] = acc0[o] + bout[o];
        out[(long long)(r0 + rb)*NOUT + o] = acc1[o] + bout[o];
    }
}

// ======================= launch ============================================
extern "C" void kernel_launch(void* const* d_in, const int* in_sizes, int n_in,
                              void* d_out, int out_size)
{
    const float* x     = (const float*)d_in[0];
    const float* noise = (const float*)d_in[1];
    const float* Wsens = (const float*)d_in[2];
    const float* bsens = (const float*)d_in[3];
    const float* Wrule = (const float*)d_in[4];
    const float* Wrec  = (const float*)d_in[5];
    const float* brec  = (const float*)d_in[6];
    const float* Wout  = (const float*)d_in[7];
    const float* bout  = (const float*)d_in[8];
    float* out = (float*)d_out;

    cudaFuncSetAttribute(kernelA, cudaFuncAttributeMaxDynamicSharedMemorySize,
                         A_SMEM_BYTES);
    cudaFuncSetAttribute(krnn, cudaFuncAttributeMaxDynamicSharedMemorySize,
                         RNN_SMEM);

    kernelA<<<dim3(16, 512), 256, A_SMEM_BYTES>>>(x, noise, Wsens, Wrule,
                                                  bsens, brec);
    kprep<<<(NH*NH)/256, 256>>>(Wrec);          // also resets g_bar
    krnn<<<NCTA, 128, RNN_SMEM>>>();            // all 256 steps, persistent
    kfinal<<<TBROWS/512, 256>>>(Wout, bout, out);
}

// round 5
// speedup vs baseline: 1.7066x; 1.1318x over previous
#include <cuda_runtime.h>
#include <cuda_bf16.h>
#include <math.h>
#include <stdint.h>

// Problem constants
#define T_STEPS 256
#define BATCH   256
#define NH      1024
#define KIN     105
#define RS      85
#define NRULE   20
#define NOUT    33
#define TBROWS  (T_STEPS*BATCH)   // 65536
#define BH      (BATCH*NH)        // 262144

// ---------------- scratch (static device allocations only) ----------------
__device__ float g_pre[(long long)TBROWS*NH];   // 256 MB
__device__ float g_hid[(long long)TBROWS*NH];   // 256 MB
__device__ __nv_bfloat16 g_Whi[NH*NH];
__device__ __nv_bfloat16 g_Wlo[NH*NH];
__device__ __nv_bfloat16 g_hhi[BH];
__device__ __nv_bfloat16 g_hlo[BH];
__device__ unsigned g_bar;

// ======================= helpers ===========================================
__device__ __forceinline__ uint32_t smem_u32(const void* p) {
    uint32_t a;
    asm("{ .reg .u64 t; cvta.to.shared.u64 t, %1; cvt.u32.u64 %0, t; }"
        : "=r"(a) : "l"(p));
    return a;
}
__device__ __forceinline__ void cp_async16(uint32_t dst, const void* src) {
    asm volatile("cp.async.cg.shared.global [%0], [%1], 16;"
                 :: "r"(dst), "l"(src) : "memory");
}
__device__ __forceinline__ void cp_commit() {
    asm volatile("cp.async.commit_group;" ::: "memory");
}
template<int N> __device__ __forceinline__ void cp_wait() {
    asm volatile("cp.async.wait_group %0;" :: "n"(N) : "memory");
}
__device__ __forceinline__ void ldmat4(uint32_t& r0, uint32_t& r1,
                                       uint32_t& r2, uint32_t& r3, uint32_t a) {
    asm volatile("ldmatrix.sync.aligned.m8n8.x4.shared.b16 {%0,%1,%2,%3}, [%4];"
                 : "=r"(r0), "=r"(r1), "=r"(r2), "=r"(r3) : "r"(a));
}
__device__ __forceinline__ void mma16816(float* c, const uint32_t* a,
                                         const uint32_t* b) {
    asm volatile(
        "mma.sync.aligned.m16n8k16.row.col.f32.bf16.bf16.f32 "
        "{%0,%1,%2,%3}, {%4,%5,%6,%7}, {%8,%9}, {%0,%1,%2,%3};"
        : "+f"(c[0]), "+f"(c[1]), "+f"(c[2]), "+f"(c[3])
        : "r"(a[0]), "r"(a[1]), "r"(a[2]), "r"(a[3]), "r"(b[0]), "r"(b[1]));
}

// ======================= kernelA: pre-activations ==========================
#define A_SA_STRIDE 132
#define A_SB_STRIDE 68
#define A_SMEM_BYTES ((105*A_SA_STRIDE + 105*A_SB_STRIDE)*4)

__global__ void kernelA(const float* __restrict__ x,
                        const float* __restrict__ noise,
                        const float* __restrict__ Wsens,
                        const float* __restrict__ Wrule,
                        const float* __restrict__ bsens,
                        const float* __restrict__ brec)
{
    extern __shared__ float sm[];
    float* sA = sm;
    float* sB = sm + 105*A_SA_STRIDE;

    const int tid = threadIdx.x;
    const int m0  = blockIdx.y * 128;
    const int n0  = blockIdx.x * 64;

    for (int idx = tid; idx < 128*105; idx += 256) {
        int m = idx / 105, k = idx - m*105;
        sA[k*A_SA_STRIDE + m] = x[(m0 + m)*KIN + k];
    }
    for (int idx = tid; idx < 64*105; idx += 256) {
        int n = idx / 105, k = idx - n*105;
        float v = (k < RS) ? Wsens[(n0 + n)*RS + k]
                           : Wrule[(n0 + n)*NRULE + (k - RS)];
        sB[k*A_SB_STRIDE + n] = v;
    }
    __syncthreads();

    const int ty = tid >> 4;
    const int tx = tid & 15;

    float acc[8][4];
#pragma unroll
    for (int i = 0; i < 8; i++)
#pragma unroll
        for (int j = 0; j < 4; j++) acc[i][j] = 0.f;

#pragma unroll 5
    for (int k = 0; k < 105; k++) {
        float4 a0 = *(const float4*)&sA[k*A_SA_STRIDE + ty*8];
        float4 a1 = *(const float4*)&sA[k*A_SA_STRIDE + ty*8 + 4];
        float4 b  = *(const float4*)&sB[k*A_SB_STRIDE + tx*4];
        float av[8] = {a0.x,a0.y,a0.z,a0.w,a1.x,a1.y,a1.z,a1.w};
        float bv[4] = {b.x,b.y,b.z,b.w};
#pragma unroll
        for (int i = 0; i < 8; i++)
#pragma unroll
            for (int j = 0; j < 4; j++)
                acc[i][j] = fmaf(av[i], bv[j], acc[i][j]);
    }

    float bias[4];
#pragma unroll
    for (int j = 0; j < 4; j++) {
        int col = n0 + tx*4 + j;
        bias[j] = bsens[col] + brec[col];
    }
#pragma unroll
    for (int i = 0; i < 8; i++) {
        int row = m0 + ty*8 + i;
        long long base = (long long)row*NH + n0 + tx*4;
#pragma unroll
        for (int j = 0; j < 4; j++)
            g_pre[base + j] = acc[i][j] + bias[j] + noise[base + j];
    }
}

// ======================= prep ==============================================
__global__ void kprep(const float* __restrict__ Wrec)
{
    int i = blockIdx.x * 256 + threadIdx.x;
    float w = Wrec[i];
    __nv_bfloat16 hi = __float2bfloat16(w);
    g_Whi[i] = hi;
    g_Wlo[i] = __float2bfloat16(w - __bfloat162float(hi));
    if (i == 0) g_bar = 0;
}

// ======================= krnn: persistent recurrence =======================
// 128 CTAs (8 m x 16 n), 256 threads (8 warps: 2m x 4n), tile 32x64.
// K=1024 in 16 chunks of 64; 4-stage cp.async pipeline, 1 sync per chunk.
// Whi n-slice persistent in smem; hhi/hlo/wlo streamed.
// 3-term double-bf16 HMMA: Ahi*Bhi + Ahi*Blo + Alo*Bhi.
#define NCTA    128
#define BM      32
#define BN      64
#define BKC     64
#define NCHUNK  16
#define NSTAGE  4
#define SM_HHI  0
#define SM_HLO  4608
#define SM_WLO  9216
#define SM_BUF  18432
#define SM_WHIP (NSTAGE*SM_BUF)              // 73728
#define WHI_PITCH 2064
#define RNN_SMEM (SM_WHIP + 64*WHI_PITCH)    // 73728 + 132096 = 205824

__device__ __forceinline__ void load_chunk(uint32_t bufb, int m0, int n0,
                                           int kc, int tid)
{
    {   // hhi + hlo : 32 rows x 64 bf16 each (256 x 16B each)
        int r  = tid >> 3;
        int ch = tid & 7;
        long long gidx = (long long)(m0 + r)*NH + kc + ch*8;
        cp_async16(bufb + SM_HHI + r*144 + ch*16, g_hhi + gidx);
        cp_async16(bufb + SM_HLO + r*144 + ch*16, g_hlo + gidx);
    }
#pragma unroll
    for (int i = 0; i < 2; i++) {   // wlo : 64 rows x 64 bf16 (512 x 16B)
        int v  = i*256 + tid;
        int r  = v >> 3;
        int ch = v & 7;
        cp_async16(bufb + SM_WLO + r*144 + ch*16,
                   g_Wlo + (long long)(n0 + r)*NH + kc + ch*8);
    }
}

__global__ void __launch_bounds__(256, 1) krnn()
{
    extern __shared__ __align__(128) char smraw[];
    const uint32_t sb  = smem_u32(smraw);
    const int tid  = threadIdx.x;
    const int wid  = tid >> 5;
    const int lane = tid & 31;
    const int wm   = wid & 1;          // m half (16 rows)
    const int wn   = wid >> 1;         // n quarter (16 cols)
    const int m0   = (blockIdx.x >> 4) * BM;
    const int n0   = (blockIdx.x & 15) * BN;

    // ---- one-time: persistent Whi slice (64 rows x 2048B) ----
#pragma unroll 1
    for (int i = 0; i < 32; i++) {
        int v  = i*256 + tid;              // 0..8191
        int r  = v >> 7;
        int ch = v & 127;
        cp_async16(sb + SM_WHIP + r*WHI_PITCH + ch*16,
                   g_Whi + (long long)(n0 + r)*NH + ch*8);
    }
    cp_commit();
    cp_wait<0>();
    __syncthreads();

    // ldmatrix lane addressing
    const int aRow  = wm*16 + (lane & 15);
    const int aKoff = ((lane >> 4) & 1) * 16;
    const int bRow  = wn*16 + ((lane >> 4) & 1)*8 + (lane & 7);
    const int bKoff = ((lane >> 3) & 1) * 16;

    // epilogue element coords
    const int rBase = m0 + wm*16 + (lane >> 2);
    const int cBase = n0 + wn*16 + (lane & 3)*2;

    float hp[2][4];
#pragma unroll
    for (int b = 0; b < 2; b++)
#pragma unroll
        for (int e = 0; e < 4; e++) hp[b][e] = 0.f;

#pragma unroll 1
    for (int t = 0; t < T_STEPS; t++) {
        float acc[2][4];
#pragma unroll
        for (int b = 0; b < 2; b++)
#pragma unroll
            for (int e = 0; e < 4; e++) acc[b][e] = 0.f;

        if (t > 0) {
            // prologue: chunks 0..2
#pragma unroll
            for (int c = 0; c < 3; c++) {
                load_chunk(sb + c*SM_BUF, m0, n0, c*BKC, tid);
                cp_commit();
            }
#pragma unroll 1
            for (int c = 0; c < NCHUNK; c++) {
                if (c < 14)       cp_wait<2>();
                else if (c == 14) cp_wait<1>();
                else              cp_wait<0>();
                __syncthreads();
                if (c < 13) {
                    load_chunk(sb + ((c + 3) & 3)*SM_BUF, m0, n0,
                               (c + 3)*BKC, tid);
                    cp_commit();
                }
                const uint32_t bb = sb + (c & 3)*SM_BUF;
#pragma unroll
                for (int q = 0; q < 4; q++) {
                    uint32_t ah[4], al[4], bh[2][2], bl[2][2];
                    uint32_t ar = aRow*144 + q*32 + aKoff;
                    ldmat4(ah[0], ah[1], ah[2], ah[3], bb + SM_HHI + ar);
                    ldmat4(al[0], al[1], al[2], al[3], bb + SM_HLO + ar);
                    ldmat4(bh[0][0], bh[0][1], bh[1][0], bh[1][1],
                           sb + SM_WHIP + bRow*WHI_PITCH
                              + c*128 + q*32 + bKoff);
                    ldmat4(bl[0][0], bl[0][1], bl[1][0], bl[1][1],
                           bb + SM_WLO + bRow*144 + q*32 + bKoff);
#pragma unroll
                    for (int ni = 0; ni < 2; ni++) {
                        mma16816(acc[ni], ah, bh[ni]);
                        mma16816(acc[ni], ah, bl[ni]);
                        mma16816(acc[ni], al, bh[ni]);
                    }
                }
            }
        }

        // ---- fused epilogue ----
        const float* __restrict__ pre = g_pre + (long long)t*BH;
        float*       __restrict__ hid = g_hid + (long long)t*BH;
#pragma unroll
        for (int ni = 0; ni < 2; ni++)
#pragma unroll
            for (int e = 0; e < 2; e++) {
                int row = rBase + e*8;
                int col = cBase + ni*8;
                long long g = (long long)row*NH + col;
                float2 pr = *(const float2*)(pre + g);
                float s0 = acc[ni][e*2+0] + pr.x;
                float s1 = acc[ni][e*2+1] + pr.y;
                float sp0 = fmaxf(s0, 0.f) + log1pf(expf(-fabsf(s0)));
                float sp1 = fmaxf(s1, 0.f) + log1pf(expf(-fabsf(s1)));
                float h0 = 0.2f*sp0 + 0.8f*hp[ni][e*2+0];
                float h1 = 0.2f*sp1 + 0.8f*hp[ni][e*2+1];
                hp[ni][e*2+0] = h0;
                hp[ni][e*2+1] = h1;
                float2 hv; hv.x = h0; hv.y = h1;
                *(float2*)(hid + g) = hv;
                __nv_bfloat16 h0h = __float2bfloat16(h0);
                __nv_bfloat16 h1h = __float2bfloat16(h1);
                uint32_t hi2 = ((uint32_t)__bfloat16_as_ushort(h1h) << 16)
                             | __bfloat16_as_ushort(h0h);
                *(uint32_t*)(g_hhi + g) = hi2;
                __nv_bfloat16 l0 = __float2bfloat16(h0 - __bfloat162float(h0h));
                __nv_bfloat16 l1 = __float2bfloat16(h1 - __bfloat162float(h1h));
                uint32_t lo2 = ((uint32_t)__bfloat16_as_ushort(l1) << 16)
                             | __bfloat16_as_ushort(l0);
                *(uint32_t*)(g_hlo + g) = lo2;
            }

        // ---- grid barrier (skip after last step) ----
        if (t < T_STEPS - 1) {
            __syncthreads();
            if (tid == 0) {
                __threadfence();
                atomicAdd(&g_bar, 1u);
                const unsigned target = (unsigned)(t + 1) * NCTA;
                unsigned v;
                do {
                    asm volatile("ld.acquire.gpu.u32 %0, [%1];"
                                 : "=r"(v) : "l"(&g_bar));
                    if (v < target) __nanosleep(64);
                } while (v < target);
            }
            __syncthreads();
        }
    }
}

// ======================= kfinal: output projection =========================
// 256 blocks x 128 threads, 2 rows/thread, float4 smem (pitch 20).
__global__ void __launch_bounds__(128) kfinal(const float* __restrict__ Wout,
                                              const float* __restrict__ bout,
                                              float* __restrict__ out)
{
    __shared__ float sA[256*20];
    __shared__ float sW[33*20];

    const int tid = threadIdx.x;          // 128
    const int r0  = blockIdx.x * 256;

    float acc0[NOUT], acc1[NOUT];
#pragma unroll
    for (int o = 0; o < NOUT; o++) { acc0[o] = 0.f; acc1[o] = 0.f; }

    const int ra = tid*2, rb = tid*2 + 1;

    for (int kc = 0; kc < NH; kc += 16) {
        __syncthreads();
#pragma unroll
        for (int i = 0; i < 8; i++) {
            int v  = i*128 + tid;          // 0..1023 float4s
            int r  = v >> 2;
            int kq = v & 3;
            float4 val = *(const float4*)&g_hid[(long long)(r0 + r)*NH + kc + kq*4];
            *(float4*)&sA[r*20 + kq*4] = val;
        }
#pragma unroll
        for (int idx = tid; idx < NOUT*16; idx += 128) {
            int o  = idx >> 4;
            int kk = idx & 15;
            sW[o*20 + kk] = Wout[o*NH + kc + kk];
        }
        __syncthreads();

        float4 a0[4], a1[4];
#pragma unroll
        for (int i = 0; i < 4; i++) {
            a0[i] = *(const float4*)&sA[ra*20 + i*4];
            a1[i] = *(const float4*)&sA[rb*20 + i*4];
        }
#pragma unroll
        for (int o = 0; o < NOUT; o++) {
#pragma unroll
            for (int i = 0; i < 4; i++) {
                float4 w = *(const float4*)&sW[o*20 + i*4];
                acc0[o] = fmaf(a0[i].x, w.x, acc0[o]);
                acc0[o] = fmaf(a0[i].y, w.y, acc0[o]);
                acc0[o] = fmaf(a0[i].z, w.z, acc0[o]);
                acc0[o] = fmaf(a0[i].w, w.w, acc0[o]);
                acc1[o] = fmaf(a1[i].x, w.x, acc1[o]);
                acc1[o] = fmaf(a1[i].y, w.y, acc1[o]);
                acc1[o] = fmaf(a1[i].z, w.z, acc1[o]);
                acc1[o] = fmaf(a1[i].w, w.w, acc1[o]);
            }
        }
    }

#pragma unroll
    for (int o = 0; o < NOUT; o++) {
        out[(long long)(r0 + ra)*NOUT + o] = acc0[o] + bout[o];
        out[(long long)(r0 + rb)*NOUT + o] = acc1[o] + bout[o];
    }
}

// ======================= launch ============================================
extern "C" void kernel_launch(void* const* d_in, const int* in_sizes, int n_in,
                              void* d_out, int out_size)
{
    const float* x     = (const float*)d_in[0];
    const float* noise = (const float*)d_in[1];
    const float* Wsens = (const float*)d_in[2];
    const float* bsens = (const float*)d_in[3];
    const float* Wrule = (const float*)d_in[4];
    const float* Wrec  = (const float*)d_in[5];
    const float* brec  = (const float*)d_in[6];
    const float* Wout  = (const float*)d_in[7];
    const float* bout  = (const float*)d_in[8];
    float* out = (float*)d_out;

    cudaFuncSetAttribute(kernelA, cudaFuncAttributeMaxDynamicSharedMemorySize,
                         A_SMEM_BYTES);
    cudaFuncSetAttribute(krnn, cudaFuncAttributeMaxDynamicSharedMemorySize,
                         RNN_SMEM);

    kernelA<<<dim3(16, 512), 256, A_SMEM_BYTES>>>(x, noise, Wsens, Wrule,
                                                  bsens, brec);
    kprep<<<(NH*NH)/256, 256>>>(Wrec);          // also resets g_bar
    krnn<<<NCTA, 256, RNN_SMEM>>>();            // all 256 steps, persistent
    kfinal<<<TBROWS/256, 128>>>(Wout, bout, out);
}

// round 6
// speedup vs baseline: 1.8609x; 1.0904x over previous
#include <cuda_runtime.h>
#include <cuda_bf16.h>
#include <math.h>
#include <stdint.h>

// Problem constants
#define T_STEPS 256
#define BATCH   256
#define NH      1024
#define KIN     105
#define KPAD    112
#define RS      85
#define NRULE   20
#define NOUT    33
#define NOPAD   48
#define TBROWS  (T_STEPS*BATCH)   // 65536
#define BH      (BATCH*NH)        // 262144

// ---------------- scratch (static device allocations only) ----------------
__device__ float g_pre[(long long)TBROWS*NH];            // 256 MB
__device__ __nv_bfloat16 g_hhi_all[(long long)TBROWS*NH]; // 128 MB
__device__ __nv_bfloat16 g_hlo_all[(long long)TBROWS*NH]; // 128 MB
__device__ __nv_bfloat16 g_Whi[NH*NH];
__device__ __nv_bfloat16 g_Wlo[NH*NH];
__device__ __nv_bfloat16 g_xhi[(long long)TBROWS*KPAD];
__device__ __nv_bfloat16 g_xlo[(long long)TBROWS*KPAD];
__device__ __nv_bfloat16 g_Wchi[NH*KPAD];
__device__ __nv_bfloat16 g_Wclo[NH*KPAD];
__device__ __nv_bfloat16 g_wouthi[NOPAD*NH];
__device__ __nv_bfloat16 g_woutlo[NOPAD*NH];
__device__ unsigned g_bar;

// ======================= helpers ===========================================
__device__ __forceinline__ uint32_t smem_u32(const void* p) {
    uint32_t a;
    asm("{ .reg .u64 t; cvta.to.shared.u64 t, %1; cvt.u32.u64 %0, t; }"
        : "=r"(a) : "l"(p));
    return a;
}
__device__ __forceinline__ void cp_async16(uint32_t dst, const void* src) {
    asm volatile("cp.async.cg.shared.global [%0], [%1], 16;"
                 :: "r"(dst), "l"(src) : "memory");
}
__device__ __forceinline__ void cp_commit() {
    asm volatile("cp.async.commit_group;" ::: "memory");
}
template<int N> __device__ __forceinline__ void cp_wait() {
    asm volatile("cp.async.wait_group %0;" :: "n"(N) : "memory");
}
__device__ __forceinline__ void ldmat4(uint32_t& r0, uint32_t& r1,
                                       uint32_t& r2, uint32_t& r3, uint32_t a) {
    asm volatile("ldmatrix.sync.aligned.m8n8.x4.shared.b16 {%0,%1,%2,%3}, [%4];"
                 : "=r"(r0), "=r"(r1), "=r"(r2), "=r"(r3) : "r"(a));
}
__device__ __forceinline__ void mma16816(float* c, const uint32_t* a,
                                         const uint32_t* b) {
    asm volatile(
        "mma.sync.aligned.m16n8k16.row.col.f32.bf16.bf16.f32 "
        "{%0,%1,%2,%3}, {%4,%5,%6,%7}, {%8,%9}, {%0,%1,%2,%3};"
        : "+f"(c[0]), "+f"(c[1]), "+f"(c[2]), "+f"(c[3])
        : "r"(a[0]), "r"(a[1]), "r"(a[2]), "r"(a[3]), "r"(b[0]), "r"(b[1]));
}

// ======================= split-prep kernels ================================
__global__ void ksplitx(const float* __restrict__ x)
{
    int idx = blockIdx.x * 256 + threadIdx.x;       // TBROWS*KPAD total
    int row = idx / KPAD;
    int k   = idx - row*KPAD;
    float v = (k < KIN) ? x[(long long)row*KIN + k] : 0.f;
    __nv_bfloat16 hi = __float2bfloat16(v);
    g_xhi[idx] = hi;
    g_xlo[idx] = __float2bfloat16(v - __bfloat162float(hi));
}

__global__ void ksplitwc(const float* __restrict__ Wsens,
                         const float* __restrict__ Wrule)
{
    int idx = blockIdx.x * 256 + threadIdx.x;       // NH*KPAD
    int n = idx / KPAD;
    int k = idx - n*KPAD;
    float v = (k < RS) ? Wsens[n*RS + k]
            : (k < KIN) ? Wrule[n*NRULE + (k - RS)] : 0.f;
    __nv_bfloat16 hi = __float2bfloat16(v);
    g_Wchi[idx] = hi;
    g_Wclo[idx] = __float2bfloat16(v - __bfloat162float(hi));
}

__global__ void ksplitwo(const float* __restrict__ Wout)
{
    int idx = blockIdx.x * 256 + threadIdx.x;       // NOPAD*NH
    int o = idx / NH;
    float v = (o < NOUT) ? Wout[idx - (o - o)*0 + (long long)0 + (o*NH + (idx - o*NH)) - o*NH + o*NH] : 0.f;
    // simplify: k = idx - o*NH
    int k = idx - o*NH;
    v = (o < NOUT) ? Wout[o*NH + k] : 0.f;
    __nv_bfloat16 hi = __float2bfloat16(v);
    g_wouthi[idx] = hi;
    g_woutlo[idx] = __float2bfloat16(v - __bfloat162float(hi));
}

__global__ void kprep(const float* __restrict__ Wrec)
{
    int i = blockIdx.x * 256 + threadIdx.x;
    float w = Wrec[i];
    __nv_bfloat16 hi = __float2bfloat16(w);
    g_Whi[i] = hi;
    g_Wlo[i] = __float2bfloat16(w - __bfloat162float(hi));
    if (i == 0) g_bar = 0;
}

// ======================= kernelA: pre-activations (HMMA) ===================
// g_pre = x @ Wc^T + b_sens + b_rec + noise.  M=65536,N=1024,K=112.
// BM=128, BN=64, 256 thr (8 warps: 4m x 2n), 3-term double-bf16.
#define A_PITCH 240
#define A_XHI 0
#define A_XLO 30720
#define A_WCH 61440
#define A_WCL 76800
#define A_SMEM 92160

__global__ void __launch_bounds__(256) kernelA(const float* __restrict__ noise,
                                               const float* __restrict__ bsens,
                                               const float* __restrict__ brec)
{
    extern __shared__ __align__(128) char smraw[];
    const uint32_t sb = smem_u32(smraw);
    const int tid  = threadIdx.x;
    const int wid  = tid >> 5;
    const int lane = tid & 31;
    const int wm   = wid & 3;
    const int wn   = wid >> 2;
    const int m0   = blockIdx.y * 128;
    const int n0   = blockIdx.x * 64;

    // loads: x tiles 128x112 (hi/lo), W tiles 64x112 (hi/lo)
#pragma unroll
    for (int i = 0; i < 7; i++) {
        int v = i*256 + tid;               // 0..1791
        int r = v / 14, ch = v - r*14;
        long long gsrc = (long long)(m0 + r)*KPAD + ch*8;
        cp_async16(sb + A_XHI + r*A_PITCH + ch*16, g_xhi + gsrc);
        cp_async16(sb + A_XLO + r*A_PITCH + ch*16, g_xlo + gsrc);
    }
#pragma unroll
    for (int i = 0; i < 4; i++) {
        int v = i*256 + tid;
        if (v < 896) {
            int r = v / 14, ch = v - r*14;
            long long gsrc = (long long)(n0 + r)*KPAD + ch*8;
            cp_async16(sb + A_WCH + r*A_PITCH + ch*16, g_Wchi + gsrc);
            cp_async16(sb + A_WCL + r*A_PITCH + ch*16, g_Wclo + gsrc);
        }
    }
    cp_commit();
    cp_wait<0>();
    __syncthreads();

    const int aKoff = ((lane >> 4) & 1) * 16;
    const int bRow  = wn*32 + ((lane >> 4) & 1)*8 + (lane & 7);
    const int bKoff = ((lane >> 3) & 1) * 16;

    float acc[2][4][4];
#pragma unroll
    for (int a = 0; a < 2; a++)
#pragma unroll
        for (int b = 0; b < 4; b++)
#pragma unroll
            for (int e = 0; e < 4; e++) acc[a][b][e] = 0.f;

#pragma unroll
    for (int k = 0; k < 7; k++) {
        uint32_t ah[2][4], al[2][4], bh[8], bl[8];
#pragma unroll
        for (int mi = 0; mi < 2; mi++) {
            uint32_t ar = (wm*32 + mi*16 + (lane & 15))*A_PITCH + k*32 + aKoff;
            ldmat4(ah[mi][0], ah[mi][1], ah[mi][2], ah[mi][3], sb + A_XHI + ar);
            ldmat4(al[mi][0], al[mi][1], al[mi][2], al[mi][3], sb + A_XLO + ar);
        }
        uint32_t br0 = bRow*A_PITCH + k*32 + bKoff;
        uint32_t br1 = (bRow + 16)*A_PITCH + k*32 + bKoff;
        ldmat4(bh[0], bh[1], bh[2], bh[3], sb + A_WCH + br0);
        ldmat4(bh[4], bh[5], bh[6], bh[7], sb + A_WCH + br1);
        ldmat4(bl[0], bl[1], bl[2], bl[3], sb + A_WCL + br0);
        ldmat4(bl[4], bl[5], bl[6], bl[7], sb + A_WCL + br1);
#pragma unroll
        for (int mi = 0; mi < 2; mi++)
#pragma unroll
            for (int ni = 0; ni < 4; ni++) {
                mma16816(acc[mi][ni], ah[mi], &bh[ni*2]);
                mma16816(acc[mi][ni], ah[mi], &bl[ni*2]);
                mma16816(acc[mi][ni], al[mi], &bh[ni*2]);
            }
    }

    // epilogue
    float2 bias[4];
#pragma unroll
    for (int ni = 0; ni < 4; ni++) {
        int col = n0 + wn*32 + ni*8 + (lane & 3)*2;
        bias[ni].x = bsens[col] + brec[col];
        bias[ni].y = bsens[col+1] + brec[col+1];
    }
#pragma unroll
    for (int mi = 0; mi < 2; mi++)
#pragma unroll
        for (int ni = 0; ni < 4; ni++)
#pragma unroll
            for (int e = 0; e < 2; e++) {
                int row = m0 + wm*32 + mi*16 + (lane >> 2) + e*8;
                int col = n0 + wn*32 + ni*8 + (lane & 3)*2;
                long long g = (long long)row*NH + col;
                float2 nz = *(const float2*)(noise + g);
                float2 o;
                o.x = acc[mi][ni][e*2+0] + bias[ni].x + nz.x;
                o.y = acc[mi][ni][e*2+1] + bias[ni].y + nz.y;
                *(float2*)(g_pre + g) = o;
            }
}

// ======================= krnn: persistent recurrence =======================
#define NCTA    128
#define BM      32
#define BN      64
#define BKC     64
#define NCHUNK  16
#define NSTAGE  4
#define SM_HHI  0
#define SM_HLO  4608
#define SM_WLO  9216
#define SM_BUF  18432
#define SM_WHIP (NSTAGE*SM_BUF)              // 73728
#define WHI_PITCH 2064
#define RNN_SMEM (SM_WHIP + 64*WHI_PITCH)    // 205824

__device__ __forceinline__ void load_h(uint32_t bufb,
                                       const __nv_bfloat16* __restrict__ hhi,
                                       const __nv_bfloat16* __restrict__ hlo,
                                       int m0, int kc, int tid)
{
    int r  = tid >> 3;
    int ch = tid & 7;
    long long gidx = (long long)(m0 + r)*NH + kc + ch*8;
    cp_async16(bufb + SM_HHI + r*144 + ch*16, hhi + gidx);
    cp_async16(bufb + SM_HLO + r*144 + ch*16, hlo + gidx);
}
__device__ __forceinline__ void load_w(uint32_t bufb, int n0, int kc, int tid)
{
#pragma unroll
    for (int i = 0; i < 2; i++) {
        int v  = i*256 + tid;
        int r  = v >> 3;
        int ch = v & 7;
        cp_async16(bufb + SM_WLO + r*144 + ch*16,
                   g_Wlo + (long long)(n0 + r)*NH + kc + ch*8);
    }
}

__global__ void __launch_bounds__(256, 1) krnn()
{
    extern __shared__ __align__(128) char smraw[];
    const uint32_t sb  = smem_u32(smraw);
    const int tid  = threadIdx.x;
    const int wid  = tid >> 5;
    const int lane = tid & 31;
    const int wm   = wid & 1;
    const int wn   = wid >> 1;
    const int m0   = (blockIdx.x >> 4) * BM;
    const int n0   = (blockIdx.x & 15) * BN;

    // one-time persistent Whi slice
#pragma unroll 1
    for (int i = 0; i < 32; i++) {
        int v  = i*256 + tid;
        int r  = v >> 7;
        int ch = v & 127;
        cp_async16(sb + SM_WHIP + r*WHI_PITCH + ch*16,
                   g_Whi + (long long)(n0 + r)*NH + ch*8);
    }
    cp_commit();
    cp_wait<0>();
    __syncthreads();

    const int aRow  = wm*16 + (lane & 15);
    const int aKoff = ((lane >> 4) & 1) * 16;
    const int bRow  = wn*16 + ((lane >> 4) & 1)*8 + (lane & 7);
    const int bKoff = ((lane >> 3) & 1) * 16;
    const int rBase = m0 + wm*16 + (lane >> 2);
    const int cBase = n0 + wn*16 + (lane & 3)*2;

    float hp[2][4];
#pragma unroll
    for (int b = 0; b < 2; b++)
#pragma unroll
        for (int e = 0; e < 4; e++) hp[b][e] = 0.f;

#pragma unroll 1
    for (int t = 0; t < T_STEPS; t++) {
        float acc[2][4];
#pragma unroll
        for (int b = 0; b < 2; b++)
#pragma unroll
            for (int e = 0; e < 4; e++) acc[b][e] = 0.f;

        if (t > 0) {
            const __nv_bfloat16* __restrict__ hhi = g_hhi_all + (long long)(t-1)*BH;
            const __nv_bfloat16* __restrict__ hlo = g_hlo_all + (long long)(t-1)*BH;
            // W for chunks 0..2 was prefetched before the barrier.
#pragma unroll
            for (int c = 0; c < 3; c++) {
                load_h(sb + c*SM_BUF, hhi, hlo, m0, c*BKC, tid);
                cp_commit();
            }
#pragma unroll 1
            for (int c = 0; c < NCHUNK; c++) {
                if (c < 14)       cp_wait<2>();
                else if (c == 14) cp_wait<1>();
                else              cp_wait<0>();
                __syncthreads();
                if (c < 13) {
                    uint32_t nb = sb + ((c + 3) & 3)*SM_BUF;
                    load_h(nb, hhi, hlo, m0, (c + 3)*BKC, tid);
                    load_w(nb, n0, (c + 3)*BKC, tid);
                    cp_commit();
                }
                const uint32_t bb = sb + (c & 3)*SM_BUF;
#pragma unroll
                for (int q = 0; q < 4; q++) {
                    uint32_t ah[4], al[4], bh[2][2], bl[2][2];
                    uint32_t ar = aRow*144 + q*32 + aKoff;
                    ldmat4(ah[0], ah[1], ah[2], ah[3], bb + SM_HHI + ar);
                    ldmat4(al[0], al[1], al[2], al[3], bb + SM_HLO + ar);
                    ldmat4(bh[0][0], bh[0][1], bh[1][0], bh[1][1],
                           sb + SM_WHIP + bRow*WHI_PITCH + c*128 + q*32 + bKoff);
                    ldmat4(bl[0][0], bl[0][1], bl[1][0], bl[1][1],
                           bb + SM_WLO + bRow*144 + q*32 + bKoff);
#pragma unroll
                    for (int ni = 0; ni < 2; ni++) {
                        mma16816(acc[ni], ah, bh[ni]);
                        mma16816(acc[ni], ah, bl[ni]);
                        mma16816(acc[ni], al, bh[ni]);
                    }
                }
            }
        }

        // prefetch next step's (step-invariant) Wlo chunks 0..2
        if (t < T_STEPS - 1) {
#pragma unroll
            for (int c = 0; c < 3; c++) {
                load_w(sb + c*SM_BUF, n0, c*BKC, tid);
                cp_commit();
            }
        }

        // ---- fused epilogue ----
        const float* __restrict__ pre = g_pre + (long long)t*BH;
        __nv_bfloat16* __restrict__ ohi = g_hhi_all + (long long)t*BH;
        __nv_bfloat16* __restrict__ olo = g_hlo_all + (long long)t*BH;
#pragma unroll
        for (int ni = 0; ni < 2; ni++)
#pragma unroll
            for (int e = 0; e < 2; e++) {
                int row = rBase + e*8;
                int col = cBase + ni*8;
                long long g = (long long)row*NH + col;
                float2 pr = *(const float2*)(pre + g);
                float s0 = acc[ni][e*2+0] + pr.x;
                float s1 = acc[ni][e*2+1] + pr.y;
                float sp0 = fmaxf(s0, 0.f) + log1pf(expf(-fabsf(s0)));
                float sp1 = fmaxf(s1, 0.f) + log1pf(expf(-fabsf(s1)));
                float h0 = 0.2f*sp0 + 0.8f*hp[ni][e*2+0];
                float h1 = 0.2f*sp1 + 0.8f*hp[ni][e*2+1];
                hp[ni][e*2+0] = h0;
                hp[ni][e*2+1] = h1;
                __nv_bfloat16 h0h = __float2bfloat16(h0);
                __nv_bfloat16 h1h = __float2bfloat16(h1);
                uint32_t hi2 = ((uint32_t)__bfloat16_as_ushort(h1h) << 16)
                             | __bfloat16_as_ushort(h0h);
                *(uint32_t*)(ohi + g) = hi2;
                __nv_bfloat16 l0 = __float2bfloat16(h0 - __bfloat162float(h0h));
                __nv_bfloat16 l1 = __float2bfloat16(h1 - __bfloat162float(h1h));
                uint32_t lo2 = ((uint32_t)__bfloat16_as_ushort(l1) << 16)
                             | __bfloat16_as_ushort(l0);
                *(uint32_t*)(olo + g) = lo2;
            }

        // ---- grid barrier ----
        if (t < T_STEPS - 1) {
            __syncthreads();
            if (tid == 0) {
                __threadfence();
                atomicAdd(&g_bar, 1u);
                const unsigned target = (unsigned)(t + 1) * NCTA;
                unsigned v;
                do {
                    asm volatile("ld.acquire.gpu.u32 %0, [%1];"
                                 : "=r"(v) : "l"(&g_bar));
                    if (v < target) __nanosleep(64);
                } while (v < target);
            }
            __syncthreads();
        }
    }
}

// ======================= kfinal: output projection (HMMA) ==================
// out = hid @ Wout^T + bout.  M=65536, N=48(pad of 33), K=1024.
// BM=128, 256 thr (8 warps, m16 each), K chunks of 64, 4-stage cp.async.
#define F_AHI 0
#define F_ALO 18432
#define F_WH  36864
#define F_WL  43776
#define F_STG 50688
#define F_SMEM (4*F_STG)   // 202752

__device__ __forceinline__ void loadf(uint32_t bufb, int m0, int kc, int tid)
{
#pragma unroll
    for (int i = 0; i < 4; i++) {
        int v  = i*256 + tid;            // 0..1023
        int r  = v >> 3;
        int ch = v & 7;
        long long gidx = (long long)(m0 + r)*NH + kc + ch*8;
        cp_async16(bufb + F_AHI + r*144 + ch*16, g_hhi_all + gidx);
        cp_async16(bufb + F_ALO + r*144 + ch*16, g_hlo_all + gidx);
    }
#pragma unroll
    for (int i = 0; i < 2; i++) {
        int v = i*256 + tid;
        if (v < 384) {
            int r  = v >> 3;
            int ch = v & 7;
            long long gidx = (long long)r*NH + kc + ch*8;
            cp_async16(bufb + F_WH + r*144 + ch*16, g_wouthi + gidx);
            cp_async16(bufb + F_WL + r*144 + ch*16, g_woutlo + gidx);
        }
    }
}

__global__ void __launch_bounds__(256, 1) kfinal(const float* __restrict__ bout,
                                                 float* __restrict__ out)
{
    extern __shared__ __align__(128) char smraw[];
    const uint32_t sb  = smem_u32(smraw);
    const int tid  = threadIdx.x;
    const int wid  = tid >> 5;
    const int lane = tid & 31;
    const int m0   = blockIdx.x * 128;

    const int aRow  = wid*16 + (lane & 15);
    const int aKoff = ((lane >> 4) & 1) * 16;
    const int bRow  = ((lane >> 4) & 1)*8 + (lane & 7);
    const int bKoff = ((lane >> 3) & 1) * 16;

    float acc[6][4];
#pragma unroll
    for (int n = 0; n < 6; n++)
#pragma unroll
        for (int e = 0; e < 4; e++) acc[n][e] = 0.f;

    // prologue: chunks 0..2
#pragma unroll
    for (int c = 0; c < 3; c++) {
        loadf(sb + c*F_STG, m0, c*BKC, tid);
        cp_commit();
    }
#pragma unroll 1
    for (int c = 0; c < 16; c++) {
        if (c < 14)       cp_wait<2>();
        else if (c == 14) cp_wait<1>();
        else              cp_wait<0>();
        __syncthreads();
        if (c < 13) {
            loadf(sb + ((c + 3) & 3)*F_STG, m0, (c + 3)*BKC, tid);
            cp_commit();
        }
        const uint32_t bb = sb + (c & 3)*F_STG;
#pragma unroll
        for (int q = 0; q < 4; q++) {
            uint32_t ah[4], al[4], bh[3][4], bl[3][4];
            uint32_t ar = aRow*144 + q*32 + aKoff;
            ldmat4(ah[0], ah[1], ah[2], ah[3], bb + F_AHI + ar);
            ldmat4(al[0], al[1], al[2], al[3], bb + F_ALO + ar);
#pragma unroll
            for (int j = 0; j < 3; j++) {
                uint32_t br = (bRow + j*16)*144 + q*32 + bKoff;
                ldmat4(bh[j][0], bh[j][1], bh[j][2], bh[j][3], bb + F_WH + br);
                ldmat4(bl[j][0], bl[j][1], bl[j][2], bl[j][3], bb + F_WL + br);
            }
#pragma unroll
            for (int ni = 0; ni < 6; ni++) {
                const uint32_t* bhp = &bh[ni >> 1][(ni & 1)*2];
                const uint32_t* blp = &bl[ni >> 1][(ni & 1)*2];
                mma16816(acc[ni], ah, bhp);
                mma16816(acc[ni], ah, blp);
                mma16816(acc[ni], al, bhp);
            }
        }
    }

    // epilogue: only cols < 33 are real
#pragma unroll
    for (int ni = 0; ni < 5; ni++)
#pragma unroll
        for (int e = 0; e < 2; e++) {
            int row = m0 + wid*16 + (lane >> 2) + e*8;
            int o   = ni*8 + (lane & 3)*2;
            if (o < NOUT)
                out[(long long)row*NOUT + o] = acc[ni][e*2+0] + bout[o];
            if (o + 1 < NOUT)
                out[(long long)row*NOUT + o + 1] = acc[ni][e*2+1] + bout[o+1];
        }
}

// ======================= launch ============================================
extern "C" void kernel_launch(void* const* d_in, const int* in_sizes, int n_in,
                              void* d_out, int out_size)
{
    const float* x     = (const float*)d_in[0];
    const float* noise = (const float*)d_in[1];
    const float* Wsens = (const float*)d_in[2];
    const float* bsens = (const float*)d_in[3];
    const float* Wrule = (const float*)d_in[4];
    const float* Wrec  = (const float*)d_in[5];
    const float* brec  = (const float*)d_in[6];
    const float* Wout  = (const float*)d_in[7];
    const float* bout  = (const float*)d_in[8];
    float* out = (float*)d_out;

    cudaFuncSetAttribute(kernelA, cudaFuncAttributeMaxDynamicSharedMemorySize,
                         A_SMEM);
    cudaFuncSetAttribute(krnn, cudaFuncAttributeMaxDynamicSharedMemorySize,
                         RNN_SMEM);
    cudaFuncSetAttribute(kfinal, cudaFuncAttributeMaxDynamicSharedMemorySize,
                         F_SMEM);

    // splits + prep
    ksplitx<<<(TBROWS*KPAD)/256, 256>>>(x);
    ksplitwc<<<(NH*KPAD)/256, 256>>>(Wsens, Wrule);
    ksplitwo<<<(NOPAD*NH)/256, 256>>>(Wout);
    kprep<<<(NH*NH)/256, 256>>>(Wrec);          // also resets g_bar

    // pre-activations (+noise +biases), HMMA
    kernelA<<<dim3(16, 512), 256, A_SMEM>>>(noise, bsens, brec);

    // persistent recurrence
    krnn<<<NCTA, 256, RNN_SMEM>>>();

    // output projection, HMMA
    kfinal<<<TBROWS/128, 256, F_SMEM>>>(bout, out);
}